// round 2
// baseline (speedup 1.0000x reference)
#include <cuda_runtime.h>
#include <math.h>

// Shapes (static)
#define Bq 4
#define Lq 2048
#define Dd 2048
#define Sn 16
#define Kt 4
#define NBi 2
#define Hn 32
#define HDi 64
#define EPSv 1e-6f

// ---------------- scratch (device globals; no allocation) ----------------
__device__ float g_q[(size_t)Bq * Lq * Dd];      // q, then ctx in place (64 MB)
__device__ float g_xb[(size_t)Bq * Lq * Dd];     // out_proj result (64 MB)
__device__ float g_logits[(size_t)Bq * Sn * Lq]; // slot-major logits
__device__ float g_xc[(size_t)Bq * Sn * Dd];     // weighted-combined x rows
__device__ float g_ws[(size_t)Bq * Sn * Dd];     // workspace state
__device__ float g_wr[(size_t)Bq * Sn * Dd];     // written
__device__ float g_kk[(size_t)Bq * Sn * Dd];
__device__ float g_vv[(size_t)Bq * Sn * Dd];

// ---------------- helpers ----------------
__device__ __forceinline__ float warp_sum(float v) {
#pragma unroll
    for (int o = 16; o; o >>= 1) v += __shfl_xor_sync(0xffffffffu, v, o);
    return v;
}

__device__ __forceinline__ float block_sum256(float v) {
    __shared__ float red[8];
    int lane = threadIdx.x & 31, warp = threadIdx.x >> 5;
    v = warp_sum(v);
    if (lane == 0) red[warp] = v;
    __syncthreads();
    if (warp == 0) {
        float r = (lane < 8) ? red[lane] : 0.0f;
        r = warp_sum(r);
        if (lane == 0) red[0] = r;
    }
    __syncthreads();
    float out = red[0];
    __syncthreads();
    return out;
}

// ---------------- init ----------------
__global__ void init_ws_kernel(const float* __restrict__ ws0) {
    int i = blockIdx.x * 256 + threadIdx.x;
    if (i < Bq * Sn * Dd) g_ws[i] = ws0[i & (Sn * Dd - 1)];  // S*D is pow2
}

// ---------------- fused RMS(x)*pre_w @ compete_w.T + compete_b ----------------
// one block per (b,l) row, 256 threads; logits written slot-major for top-k
__global__ void rms_logits_kernel(const float* __restrict__ x,
                                  const float* __restrict__ pre_w,
                                  const float* __restrict__ cw,
                                  const float* __restrict__ cb) {
    __shared__ float sx[Dd];
    int row = blockIdx.x;
    const float* xr = x + (size_t)row * Dd;
    float ss = 0.0f;
    for (int i = threadIdx.x; i < Dd; i += 256) {
        float v = xr[i];
        sx[i] = v * pre_w[i];   // dot operand; rms uses raw x*x
        ss += v * v;
    }
    ss = block_sum256(ss);      // also orders sx writes
    float inv = rsqrtf(ss * (1.0f / Dd) + EPSv);
    int warp = threadIdx.x >> 5, lane = threadIdx.x & 31;
    int b = row / Lq, l = row % Lq;
    for (int s = warp; s < Sn; s += 8) {
        const float* cwr = cw + (size_t)s * Dd;
        float acc = 0.0f;
        for (int i = lane; i < Dd; i += 32) acc += sx[i] * cwr[i];
        acc = warp_sum(acc);
        if (lane == 0) g_logits[((size_t)(b * Sn + s)) * Lq + l] = acc * inv + cb[s];
    }
}

// ---------------- top-4 over tokens per (b,slot) + softmax + weighted x-combo ----------------
__device__ __forceinline__ bool tk_better(float v1, int i1, float v2, int i2) {
    return (v1 > v2) || (v1 == v2 && i1 < i2);
}

__global__ void topk_xc_kernel(const float* __restrict__ x) {
    int bs = blockIdx.x;            // b*S + s
    int b = bs / Sn;
    const float* lg = g_logits + (size_t)bs * Lq;
    float lv[4] = {-3.402823466e38f, -3.402823466e38f, -3.402823466e38f, -3.402823466e38f};
    int li[4] = {0x7fffffff, 0x7fffffff, 0x7fffffff, 0x7fffffff};
    for (int l = threadIdx.x; l < Lq; l += 256) {
        float v = lg[l];
        if (tk_better(v, l, lv[3], li[3])) {
            lv[3] = v; li[3] = l;
#pragma unroll
            for (int k = 3; k > 0; --k) {
                if (tk_better(lv[k], li[k], lv[k - 1], li[k - 1])) {
                    float tv = lv[k]; lv[k] = lv[k - 1]; lv[k - 1] = tv;
                    int ti = li[k]; li[k] = li[k - 1]; li[k - 1] = ti;
                }
            }
        }
    }
    __shared__ float sv[256 * 4];
    __shared__ int si[256 * 4];
#pragma unroll
    for (int k = 0; k < 4; k++) { sv[threadIdx.x * 4 + k] = lv[k]; si[threadIdx.x * 4 + k] = li[k]; }
    for (int off = 128; off >= 1; off >>= 1) {
        __syncthreads();
        if (threadIdx.x < off) {
            float av[4], bv[4]; int ai[4], bi[4];
#pragma unroll
            for (int k = 0; k < 4; k++) {
                av[k] = sv[threadIdx.x * 4 + k]; ai[k] = si[threadIdx.x * 4 + k];
                bv[k] = sv[(threadIdx.x + off) * 4 + k]; bi[k] = si[(threadIdx.x + off) * 4 + k];
            }
            float ov[4]; int oi[4];
            int ia = 0, ib = 0;
#pragma unroll
            for (int k = 0; k < 4; k++) {
                bool ta = (ib >= 4) || (ia < 4 && tk_better(av[ia], ai[ia], bv[ib], bi[ib]));
                if (ta) { ov[k] = av[ia]; oi[k] = ai[ia]; ia++; }
                else    { ov[k] = bv[ib]; oi[k] = bi[ib]; ib++; }
            }
#pragma unroll
            for (int k = 0; k < 4; k++) { sv[threadIdx.x * 4 + k] = ov[k]; si[threadIdx.x * 4 + k] = oi[k]; }
        }
    }
    __syncthreads();
    __shared__ float swgt[4];
    __shared__ int sidx[4];
    if (threadIdx.x == 0) {
        float m = sv[0];  // sorted descending
        float e[4], sum = 0.0f;
#pragma unroll
        for (int k = 0; k < 4; k++) { e[k] = expf(sv[k] - m); sum += e[k]; }
#pragma unroll
        for (int k = 0; k < 4; k++) { swgt[k] = e[k] / sum; sidx[k] = si[k]; }
    }
    __syncthreads();
    float w0 = swgt[0], w1 = swgt[1], w2 = swgt[2], w3 = swgt[3];
    const float* x0 = x + ((size_t)b * Lq + sidx[0]) * Dd;
    const float* x1 = x + ((size_t)b * Lq + sidx[1]) * Dd;
    const float* x2 = x + ((size_t)b * Lq + sidx[2]) * Dd;
    const float* x3 = x + ((size_t)b * Lq + sidx[3]) * Dd;
    float* xc = g_xc + (size_t)bs * Dd;
    for (int d = threadIdx.x; d < Dd; d += 256)
        xc[d] = w0 * x0[d] + w1 * x1[d] + w2 * x2[d] + w3 * x3[d];
}

// ---------------- small GEMM: C[64,2048] = A[64,2048] @ W[2048,2048]^T + bias ----------------
// grid (2048/64, 64/16), 256 threads. A/C selected by code (0: xc->wr, 1: ws->kk, 2: ws->vv)
__global__ void gemm_small_kernel(int which,
                                  const float* __restrict__ W,
                                  const float* __restrict__ bias) {
    const float* A = (which == 0) ? g_xc : g_ws;
    float* C = (which == 0) ? g_wr : (which == 1) ? g_kk : g_vv;
    __shared__ float As[16][65];
    __shared__ float Ws[64][65];
    int n0 = blockIdx.x * 64, m0 = blockIdx.y * 16;
    int tid = threadIdx.x;
    int ar = tid >> 4, ac = (tid & 15) * 4;
    int tx = tid & 63, ty = tid >> 6;
    float acc[4] = {0, 0, 0, 0};
    for (int k0 = 0; k0 < Dd; k0 += 64) {
        float4 a = *(const float4*)(A + (size_t)(m0 + ar) * Dd + k0 + ac);
        As[ar][ac + 0] = a.x; As[ar][ac + 1] = a.y; As[ar][ac + 2] = a.z; As[ar][ac + 3] = a.w;
#pragma unroll
        for (int q = 0; q < 4; q++) {
            int wr = ar + q * 16;
            float4 w = *(const float4*)(W + (size_t)(n0 + wr) * Dd + k0 + ac);
            Ws[ac + 0][wr] = w.x; Ws[ac + 1][wr] = w.y; Ws[ac + 2][wr] = w.z; Ws[ac + 3][wr] = w.w;
        }
        __syncthreads();
#pragma unroll
        for (int k = 0; k < 64; k++) {
            float wv = Ws[k][tx];
#pragma unroll
            for (int i = 0; i < 4; i++) acc[i] += As[ty * 4 + i][k] * wv;
        }
        __syncthreads();
    }
    float bv = bias[n0 + tx];
#pragma unroll
    for (int i = 0; i < 4; i++)
        C[(size_t)(m0 + ty * 4 + i) * Dd + n0 + tx] = acc[i] + bv;
}

// ---------------- ws = RMS(ws + written, post_w) in place ----------------
__global__ void ws_update_kernel(const float* __restrict__ post_w) {
    int r = blockIdx.x;
    __shared__ float srow[Dd];
    float* wsr = g_ws + (size_t)r * Dd;
    const float* wrr = g_wr + (size_t)r * Dd;
    float ss = 0.0f;
    for (int i = threadIdx.x; i < Dd; i += 256) {
        float v = wsr[i] + wrr[i];
        srow[i] = v;
        ss += v * v;
    }
    ss = block_sum256(ss);
    float inv = rsqrtf(ss * (1.0f / Dd) + EPSv);
    for (int i = threadIdx.x; i < Dd; i += 256) wsr[i] = srow[i] * inv * post_w[i];
}

// ---------------- big SGEMM: C[M,2048] = A[M,2048] @ W[2048,2048]^T + bias ----------------
// 128x128x8 tiles, 8x8 micro-tile, 256 threads, double-buffered smem (one barrier/K-step)
__global__ void __launch_bounds__(256, 2)
sgemm_kernel(const float* __restrict__ A, const float* __restrict__ W,
             const float* __restrict__ bias, float* __restrict__ C) {
    __shared__ float As[2][8][132];
    __shared__ float Bs[2][8][132];
    int tid = threadIdx.x;
    int m0 = blockIdx.y * 128, n0 = blockIdx.x * 128;
    int lr = tid >> 1, lc = (tid & 1) * 4;
    const float* Ap = A + (size_t)(m0 + lr) * Dd + lc;
    const float* Wp = W + (size_t)(n0 + lr) * Dd + lc;
    float4 a = *(const float4*)Ap;
    float4 b = *(const float4*)Wp;
    float acc[8][8];
#pragma unroll
    for (int i = 0; i < 8; i++)
#pragma unroll
        for (int j = 0; j < 8; j++) acc[i][j] = 0.0f;
    int tx = tid & 15, ty = tid >> 4;
    int mo = ty * 8, no = tx * 8;
    int buf = 0;
    As[0][lc + 0][lr] = a.x; As[0][lc + 1][lr] = a.y; As[0][lc + 2][lr] = a.z; As[0][lc + 3][lr] = a.w;
    Bs[0][lc + 0][lr] = b.x; Bs[0][lc + 1][lr] = b.y; Bs[0][lc + 2][lr] = b.z; Bs[0][lc + 3][lr] = b.w;
    __syncthreads();
    for (int k0 = 0; k0 < Dd; k0 += 8) {
        int k1 = k0 + 8;
        if (k1 < Dd) {
            a = *(const float4*)(Ap + k1);
            b = *(const float4*)(Wp + k1);
        }
#pragma unroll
        for (int kk = 0; kk < 8; kk++) {
            float ar[8], br[8];
#pragma unroll
            for (int i = 0; i < 8; i++) ar[i] = As[buf][kk][mo + i];
#pragma unroll
            for (int j = 0; j < 8; j++) br[j] = Bs[buf][kk][no + j];
#pragma unroll
            for (int i = 0; i < 8; i++)
#pragma unroll
                for (int j = 0; j < 8; j++) acc[i][j] += ar[i] * br[j];
        }
        if (k1 < Dd) {
            int nb = buf ^ 1;
            As[nb][lc + 0][lr] = a.x; As[nb][lc + 1][lr] = a.y;
            As[nb][lc + 2][lr] = a.z; As[nb][lc + 3][lr] = a.w;
            Bs[nb][lc + 0][lr] = b.x; Bs[nb][lc + 1][lr] = b.y;
            Bs[nb][lc + 2][lr] = b.z; Bs[nb][lc + 3][lr] = b.w;
            __syncthreads();
            buf = nb;
        }
    }
    float bv[8];
#pragma unroll
    for (int j = 0; j < 8; j++) bv[j] = bias[n0 + no + j];
#pragma unroll
    for (int i = 0; i < 8; i++) {
        float* Cp = C + (size_t)(m0 + mo + i) * Dd + n0 + no;
        float4 o0, o1;
        o0.x = acc[i][0] + bv[0]; o0.y = acc[i][1] + bv[1];
        o0.z = acc[i][2] + bv[2]; o0.w = acc[i][3] + bv[3];
        o1.x = acc[i][4] + bv[4]; o1.y = acc[i][5] + bv[5];
        o1.z = acc[i][6] + bv[6]; o1.w = acc[i][7] + bv[7];
        *(float4*)Cp = o0;
        *(float4*)(Cp + 4) = o1;
    }
}

// ---------------- attention over S=16 slots; q -> ctx in place ----------------
// grid (L/128, H, B), 256 threads; k/v slice for (b,h) staged in smem
__global__ void attn_kernel() {
    __shared__ float skk[Sn * HDi];
    __shared__ float svv[Sn * HDi];
    int chunk = blockIdx.x, h = blockIdx.y, b = blockIdx.z;
    int tid = threadIdx.x;
    for (int i = tid; i < Sn * HDi; i += 256) {
        int s = i >> 6, d = i & 63;
        size_t off = ((size_t)(b * Sn + s)) * Dd + h * HDi + d;
        skk[i] = g_kk[off];
        svv[i] = g_vv[off];
    }
    __syncthreads();
    int warp = tid >> 5, lane = tid & 31;
    for (int t = 0; t < 16; t++) {
        int l = chunk * 128 + warp * 16 + t;
        float* qp = g_q + ((size_t)b * Lq + l) * Dd + h * HDi;
        float q0 = qp[lane], q1 = qp[lane + 32];
        float e[16];
        float m = -1e30f;
#pragma unroll
        for (int s = 0; s < Sn; s++) {
            float p = q0 * skk[s * 64 + lane] + q1 * skk[s * 64 + lane + 32];
#pragma unroll
            for (int o = 16; o; o >>= 1) p += __shfl_xor_sync(0xffffffffu, p, o);
            p *= 0.125f;  // 1/sqrt(64)
            e[s] = p;
            m = fmaxf(m, p);
        }
        float sum = 0.0f;
#pragma unroll
        for (int s = 0; s < Sn; s++) { e[s] = __expf(e[s] - m); sum += e[s]; }
        float inv = 1.0f / sum;
        float c0 = 0.0f, c1 = 0.0f;
#pragma unroll
        for (int s = 0; s < Sn; s++) {
            c0 += e[s] * svv[s * 64 + lane];
            c1 += e[s] * svv[s * 64 + lane + 32];
        }
        qp[lane] = c0 * inv;
        qp[lane + 32] = c1 * inv;
    }
}

// ---------------- x = RMS(x + x_b, post_w) in place ----------------
__global__ void resid_rms_kernel(float* __restrict__ x, const float* __restrict__ post_w) {
    int r = blockIdx.x;
    __shared__ float srow[Dd];
    float* xr = x + (size_t)r * Dd;
    const float* br = g_xb + (size_t)r * Dd;
    float ss = 0.0f;
    for (int i = threadIdx.x; i < Dd; i += 256) {
        float v = xr[i] + br[i];
        srow[i] = v;
        ss += v * v;
    }
    ss = block_sum256(ss);
    float inv = rsqrtf(ss * (1.0f / Dd) + EPSv);
    for (int i = threadIdx.x; i < Dd; i += 256) xr[i] = srow[i] * inv * post_w[i];
}

// q GEMM reads x, writes g_q; out GEMM reads g_q, writes g_xb — wrappers so the
// host path needs no symbol-address queries at all.
__global__ void __launch_bounds__(256, 2) noop_kernel() {}

// ---------------- host orchestration ----------------
extern "C" void kernel_launch(void* const* d_in, const int* in_sizes, int n_in,
                              void* d_out, int out_size) {
    const float* x_in       = (const float*)d_in[0];
    const float* ws0        = (const float*)d_in[1];
    const float* compete_w  = (const float*)d_in[2];
    const float* compete_b  = (const float*)d_in[3];
    const float* write_w    = (const float*)d_in[4];
    const float* write_b    = (const float*)d_in[5];
    const float* in_proj_w  = (const float*)d_in[6];
    const float* in_proj_b  = (const float*)d_in[7];
    const float* out_proj_w = (const float*)d_in[8];
    const float* out_proj_b = (const float*)d_in[9];
    // d_in[10], d_in[11]: ig_w/ig_b — dead code in reference, unused
    const float* pre_w      = (const float*)d_in[12];
    const float* post_w     = (const float*)d_in[13];
    float* x = (float*)d_out;

    // device-global addresses for the two big GEMM operands; resolved once per
    // process (static), outside any capture-sensitive path.
    static float* p_q = nullptr;
    static float* p_xb = nullptr;
    if (!p_q) {
        void* tmp;
        cudaGetSymbolAddress(&tmp, g_q);  (void)0; p_q  = (float*)tmp;
        cudaGetSymbolAddress(&tmp, g_xb); p_xb = (float*)tmp;
    }

    cudaMemcpyAsync(x, x_in, sizeof(float) * (size_t)Bq * Lq * Dd, cudaMemcpyDeviceToDevice);
    init_ws_kernel<<<(Bq * Sn * Dd + 255) / 256, 256>>>(ws0);

    for (int it = 0; it < NBi; ++it) {
        // competition logits from RMS(x)
        rms_logits_kernel<<<Bq * Lq, 256>>>(x, pre_w, compete_w, compete_b);
        // top-4 tokens per slot + softmax + weighted x combination (linearity trick)
        topk_xc_kernel<<<Bq * Sn, 256>>>(x);
        // written = xc @ write_w.T + write_b  (64-row GEMM, not 8192)
        gemm_small_kernel<<<dim3(Dd / 64, 4), 256>>>(0, write_w, write_b);
        // ws = RMS(ws + written)
        ws_update_kernel<<<Bq * Sn, 256>>>(post_w);
        // kk / vv from ws (64-row GEMMs)
        gemm_small_kernel<<<dim3(Dd / 64, 4), 256>>>(1, in_proj_w + (size_t)Dd * Dd, in_proj_b + Dd);
        gemm_small_kernel<<<dim3(Dd / 64, 4), 256>>>(2, in_proj_w + 2 * (size_t)Dd * Dd, in_proj_b + 2 * Dd);
        // q = x @ wq.T + bq  (big GEMM #1)
        sgemm_kernel<<<dim3(Dd / 128, (Bq * Lq) / 128), 256>>>(x, in_proj_w, in_proj_b, p_q);
        // attention over 16 slots; ctx overwrites q in place
        attn_kernel<<<dim3(Lq / 128, Hn, Bq), 256>>>();
        // x_b = ctx @ out_proj_w.T + out_proj_b  (big GEMM #2)
        sgemm_kernel<<<dim3(Dd / 128, (Bq * Lq) / 128), 256>>>(p_q, out_proj_w, out_proj_b, p_xb);
        // x = RMS(x + x_b)
        resid_rms_kernel<<<Bq * Lq, 256>>>(x, post_w);
        // ignition: sigmoid(x @ ig_w.T + ig_b) — result unused by reference; skipped
    }
}

// round 4
// speedup vs baseline: 2.1526x; 2.1526x over previous
#include <cuda_runtime.h>
#include <cuda_bf16.h>
#include <math.h>
#include <stdint.h>

// Shapes (static)
#define Bq 4
#define Lq 2048
#define Dd 2048
#define Sn 16
#define Kt 4
#define NBi 2
#define Hn 32
#define HDi 64
#define EPSv 1e-6f
#define KS 4   // split-K factor for small GEMMs

// ---------------- scratch (device globals; no allocation) ----------------
__device__ float g_q[(size_t)Bq * Lq * Dd];      // q, then ctx in place (64 MB)
__device__ float g_xb[(size_t)Bq * Lq * Dd];     // out_proj result (64 MB)
__device__ float g_logits[(size_t)Bq * Sn * Lq]; // slot-major logits
__device__ float g_xc[(size_t)Bq * Sn * Dd];     // weighted-combined x rows
__device__ float g_ws[(size_t)Bq * Sn * Dd];     // workspace state
__device__ float g_wr[(size_t)Bq * Sn * Dd];     // written
__device__ float g_kk[(size_t)Bq * Sn * Dd];
__device__ float g_vv[(size_t)Bq * Sn * Dd];
__device__ float g_part[2][KS][64 * Dd];         // split-K partials (4 MB)

// bf16 hi/lo split operands for tensor-core GEMMs
__device__ __align__(128) __nv_bfloat16 g_ahi[(size_t)Bq * Lq * Dd];
__device__ __align__(128) __nv_bfloat16 g_alo[(size_t)Bq * Lq * Dd];
__device__ __align__(128) __nv_bfloat16 g_wqhi[(size_t)Dd * Dd];
__device__ __align__(128) __nv_bfloat16 g_wqlo[(size_t)Dd * Dd];
__device__ __align__(128) __nv_bfloat16 g_wohi[(size_t)Dd * Dd];
__device__ __align__(128) __nv_bfloat16 g_wolo[(size_t)Dd * Dd];

// ---------------- PTX helpers (sm_80-compatible: cp.async / ldmatrix / mma) ----------------
__device__ __forceinline__ uint32_t smem_u32(const void* p) {
    return (uint32_t)__cvta_generic_to_shared(p);
}

__device__ __forceinline__ void cpasync16(uint32_t dst, const void* src) {
    asm volatile("cp.async.cg.shared.global [%0], [%1], 16;\n" :: "r"(dst), "l"(src));
}
#define CP_COMMIT() asm volatile("cp.async.commit_group;\n" ::: "memory")
#define CP_WAIT0()  asm volatile("cp.async.wait_group 0;\n" ::: "memory")

__device__ __forceinline__ void ldsm4(uint32_t* r, uint32_t addr) {
    asm volatile("ldmatrix.sync.aligned.m8n8.x4.shared.b16 {%0,%1,%2,%3}, [%4];\n"
                 : "=r"(r[0]), "=r"(r[1]), "=r"(r[2]), "=r"(r[3]) : "r"(addr));
}

__device__ __forceinline__ void mma16816(float* c, const uint32_t* a, uint32_t b0, uint32_t b1) {
    asm volatile(
        "mma.sync.aligned.m16n8k16.row.col.f32.bf16.bf16.f32 "
        "{%0,%1,%2,%3}, {%4,%5,%6,%7}, {%8,%9}, {%0,%1,%2,%3};\n"
        : "+f"(c[0]), "+f"(c[1]), "+f"(c[2]), "+f"(c[3])
        : "r"(a[0]), "r"(a[1]), "r"(a[2]), "r"(a[3]), "r"(b0), "r"(b1));
}

// ---------------- generic helpers ----------------
__device__ __forceinline__ float warp_sum(float v) {
#pragma unroll
    for (int o = 16; o; o >>= 1) v += __shfl_xor_sync(0xffffffffu, v, o);
    return v;
}

__device__ __forceinline__ float block_sum256(float v) {
    __shared__ float red[8];
    int lane = threadIdx.x & 31, warp = threadIdx.x >> 5;
    v = warp_sum(v);
    if (lane == 0) red[warp] = v;
    __syncthreads();
    if (warp == 0) {
        float r = (lane < 8) ? red[lane] : 0.0f;
        r = warp_sum(r);
        if (lane == 0) red[0] = r;
    }
    __syncthreads();
    float out = red[0];
    __syncthreads();
    return out;
}

// ---------------- init ----------------
__global__ void init_ws_kernel(const float* __restrict__ ws0) {
    int i = blockIdx.x * 256 + threadIdx.x;
    if (i < Bq * Sn * Dd) g_ws[i] = ws0[i & (Sn * Dd - 1)];
}

// ---------------- fp32 -> bf16 hi/lo split (vectorized) ----------------
__global__ void conv_split_kernel(const float* __restrict__ src,
                                  __nv_bfloat16* __restrict__ hi,
                                  __nv_bfloat16* __restrict__ lo, int n4) {
    int i = blockIdx.x * 256 + threadIdx.x;
    if (i >= n4) return;
    float4 f = ((const float4*)src)[i];
    __nv_bfloat162 h01 = __floats2bfloat162_rn(f.x, f.y);
    __nv_bfloat162 h23 = __floats2bfloat162_rn(f.z, f.w);
    float2 hf01 = __bfloat1622float2(h01);
    float2 hf23 = __bfloat1622float2(h23);
    __nv_bfloat162 l01 = __floats2bfloat162_rn(f.x - hf01.x, f.y - hf01.y);
    __nv_bfloat162 l23 = __floats2bfloat162_rn(f.z - hf23.x, f.w - hf23.y);
    uint2 hv, lv;
    hv.x = *(uint32_t*)&h01; hv.y = *(uint32_t*)&h23;
    lv.x = *(uint32_t*)&l01; lv.y = *(uint32_t*)&l23;
    ((uint2*)hi)[i] = hv;
    ((uint2*)lo)[i] = lv;
}

// ---------------- fused RMS(x)*pre_w @ compete_w.T + compete_b ----------------
__global__ void rms_logits_kernel(const float* __restrict__ x,
                                  const float* __restrict__ pre_w,
                                  const float* __restrict__ cw,
                                  const float* __restrict__ cb) {
    __shared__ float sx[Dd];
    int row = blockIdx.x;
    const float* xr = x + (size_t)row * Dd;
    float ss = 0.0f;
    for (int i = threadIdx.x; i < Dd; i += 256) {
        float v = xr[i];
        sx[i] = v * pre_w[i];
        ss += v * v;
    }
    ss = block_sum256(ss);
    float inv = rsqrtf(ss * (1.0f / Dd) + EPSv);
    int warp = threadIdx.x >> 5, lane = threadIdx.x & 31;
    int b = row / Lq, l = row % Lq;
    for (int s = warp; s < Sn; s += 8) {
        const float* cwr = cw + (size_t)s * Dd;
        float acc = 0.0f;
        for (int i = lane; i < Dd; i += 32) acc += sx[i] * cwr[i];
        acc = warp_sum(acc);
        if (lane == 0) g_logits[((size_t)(b * Sn + s)) * Lq + l] = acc * inv + cb[s];
    }
}

// ---------------- top-4 per (b,slot) + softmax + weighted x-combo ----------------
__device__ __forceinline__ bool tk_better(float v1, int i1, float v2, int i2) {
    return (v1 > v2) || (v1 == v2 && i1 < i2);
}

__global__ void topk_xc_kernel(const float* __restrict__ x) {
    int bs = blockIdx.x;
    int b = bs / Sn;
    const float* lg = g_logits + (size_t)bs * Lq;
    float lv[4] = {-3.402823466e38f, -3.402823466e38f, -3.402823466e38f, -3.402823466e38f};
    int li[4] = {0x7fffffff, 0x7fffffff, 0x7fffffff, 0x7fffffff};
    for (int l = threadIdx.x; l < Lq; l += 256) {
        float v = lg[l];
        if (tk_better(v, l, lv[3], li[3])) {
            lv[3] = v; li[3] = l;
#pragma unroll
            for (int k = 3; k > 0; --k) {
                if (tk_better(lv[k], li[k], lv[k - 1], li[k - 1])) {
                    float tv = lv[k]; lv[k] = lv[k - 1]; lv[k - 1] = tv;
                    int ti = li[k]; li[k] = li[k - 1]; li[k - 1] = ti;
                }
            }
        }
    }
    __shared__ float sv[256 * 4];
    __shared__ int si[256 * 4];
#pragma unroll
    for (int k = 0; k < 4; k++) { sv[threadIdx.x * 4 + k] = lv[k]; si[threadIdx.x * 4 + k] = li[k]; }
    for (int off = 128; off >= 1; off >>= 1) {
        __syncthreads();
        if (threadIdx.x < off) {
            float av[4], bv[4]; int ai[4], bi[4];
#pragma unroll
            for (int k = 0; k < 4; k++) {
                av[k] = sv[threadIdx.x * 4 + k]; ai[k] = si[threadIdx.x * 4 + k];
                bv[k] = sv[(threadIdx.x + off) * 4 + k]; bi[k] = si[(threadIdx.x + off) * 4 + k];
            }
            float ov[4]; int oi[4];
            int ia = 0, ib = 0;
#pragma unroll
            for (int k = 0; k < 4; k++) {
                bool ta = (ib >= 4) || (ia < 4 && tk_better(av[ia], ai[ia], bv[ib], bi[ib]));
                if (ta) { ov[k] = av[ia]; oi[k] = ai[ia]; ia++; }
                else    { ov[k] = bv[ib]; oi[k] = bi[ib]; ib++; }
            }
#pragma unroll
            for (int k = 0; k < 4; k++) { sv[threadIdx.x * 4 + k] = ov[k]; si[threadIdx.x * 4 + k] = oi[k]; }
        }
    }
    __syncthreads();
    __shared__ float swgt[4];
    __shared__ int sidx[4];
    if (threadIdx.x == 0) {
        float m = sv[0];
        float e[4], sum = 0.0f;
#pragma unroll
        for (int k = 0; k < 4; k++) { e[k] = expf(sv[k] - m); sum += e[k]; }
#pragma unroll
        for (int k = 0; k < 4; k++) { swgt[k] = e[k] / sum; sidx[k] = si[k]; }
    }
    __syncthreads();
    float w0 = swgt[0], w1 = swgt[1], w2 = swgt[2], w3 = swgt[3];
    const float* x0 = x + ((size_t)b * Lq + sidx[0]) * Dd;
    const float* x1 = x + ((size_t)b * Lq + sidx[1]) * Dd;
    const float* x2 = x + ((size_t)b * Lq + sidx[2]) * Dd;
    const float* x3 = x + ((size_t)b * Lq + sidx[3]) * Dd;
    float* xc = g_xc + (size_t)bs * Dd;
    for (int d = threadIdx.x; d < Dd; d += 256)
        xc[d] = w0 * x0[d] + w1 * x1[d] + w2 * x2[d] + w3 * x3[d];
}

// ---------------- small GEMM, split-K ----------------
__global__ void gemm_small_split(int which, const float* __restrict__ Wbase) {
    int z = blockIdx.z;
    int zi = z / KS, kz = z % KS;
    const float* A = (which == 0) ? g_xc : g_ws;
    const float* W = Wbase + (size_t)zi * Dd * Dd;
    __shared__ float As[16][65];
    __shared__ float Ws[64][65];
    int n0 = blockIdx.x * 64, m0 = blockIdx.y * 16;
    int tid = threadIdx.x;
    int ar = tid >> 4, ac = (tid & 15) * 4;
    int tx = tid & 63, ty = tid >> 6;
    float acc[4] = {0, 0, 0, 0};
    int kbeg = kz * (Dd / KS), kend = kbeg + Dd / KS;
    for (int k0 = kbeg; k0 < kend; k0 += 64) {
        float4 a = *(const float4*)(A + (size_t)(m0 + ar) * Dd + k0 + ac);
        As[ar][ac + 0] = a.x; As[ar][ac + 1] = a.y; As[ar][ac + 2] = a.z; As[ar][ac + 3] = a.w;
#pragma unroll
        for (int q = 0; q < 4; q++) {
            int wr = ar + q * 16;
            float4 w = *(const float4*)(W + (size_t)(n0 + wr) * Dd + k0 + ac);
            Ws[ac + 0][wr] = w.x; Ws[ac + 1][wr] = w.y; Ws[ac + 2][wr] = w.z; Ws[ac + 3][wr] = w.w;
        }
        __syncthreads();
#pragma unroll
        for (int k = 0; k < 64; k++) {
            float wv = Ws[k][tx];
#pragma unroll
            for (int i = 0; i < 4; i++) acc[i] += As[ty * 4 + i][k] * wv;
        }
        __syncthreads();
    }
    float* P = g_part[zi][kz];
#pragma unroll
    for (int i = 0; i < 4; i++)
        P[(size_t)(m0 + ty * 4 + i) * Dd + n0 + tx] = acc[i];
}

__global__ void gemm_small_reduce(int which, const float* __restrict__ bias) {
    int zi = blockIdx.y;
    int i = blockIdx.x * 256 + threadIdx.x;
    float s = g_part[zi][0][i] + g_part[zi][1][i] + g_part[zi][2][i] + g_part[zi][3][i];
    s += bias[(size_t)zi * Dd + (i & (Dd - 1))];
    float* C = (which == 0) ? g_wr : (zi == 0 ? g_kk : g_vv);
    C[i] = s;
}

// ---------------- ws = RMS(ws + written, post_w) in place ----------------
__global__ void ws_update_kernel(const float* __restrict__ post_w) {
    int r = blockIdx.x;
    __shared__ float srow[Dd];
    float* wsr = g_ws + (size_t)r * Dd;
    const float* wrr = g_wr + (size_t)r * Dd;
    float ss = 0.0f;
    for (int i = threadIdx.x; i < Dd; i += 256) {
        float v = wsr[i] + wrr[i];
        srow[i] = v;
        ss += v * v;
    }
    ss = block_sum256(ss);
    float inv = rsqrtf(ss * (1.0f / Dd) + EPSv);
    for (int i = threadIdx.x; i < Dd; i += 256) wsr[i] = srow[i] * inv * post_w[i];
}

// ---------------- HMMA bf16x3 GEMM: C[8192,2048] = A @ W^T + bias ----------------
// CTA 128x128, 8 warps (2M x 4N), warp tile 64x32 via m16n8k16.
// K-chunks of 32, 2-stage cp.async double buffer.
// Smem rows pitched at 80B: row quads hit distinct 16B bank groups mod 8 -> conflict-free ldmatrix.
#define PITCH 80
#define TILE_BYTES (128 * PITCH)       // 10240
#define STAGE_BYTES (4 * TILE_BYTES)   // 40960 (Ahi, Alo, Whi, Wlo)
#define HSMEM (2 * STAGE_BYTES)        // 81920

static __device__ __forceinline__ void load_stage(
        uint32_t sbase, int stage,
        const __nv_bfloat16* __restrict__ Ahi, const __nv_bfloat16* __restrict__ Alo,
        const __nv_bfloat16* __restrict__ Whi, const __nv_bfloat16* __restrict__ Wlo,
        size_t m0, size_t n0, int c, int tid) {
    uint32_t st = sbase + (uint32_t)stage * STAGE_BYTES;
    int kb = c * 32;
#pragma unroll
    for (int h = 0; h < 2; h++) {
        int e = tid + h * 256;
        int row = e >> 2, q = e & 3;
        uint32_t so = (uint32_t)row * PITCH + (uint32_t)q * 16;
        size_t goff = (size_t)row * Dd + kb + q * 8;
        cpasync16(st + so,                  Ahi + (m0 * Dd + goff));
        cpasync16(st + TILE_BYTES + so,     Alo + (m0 * Dd + goff));
        cpasync16(st + 2 * TILE_BYTES + so, Whi + (n0 * Dd + goff));
        cpasync16(st + 3 * TILE_BYTES + so, Wlo + (n0 * Dd + goff));
    }
}

__global__ void __launch_bounds__(256, 1)
gemm_bf16_kernel(const __nv_bfloat16* __restrict__ Ahi, const __nv_bfloat16* __restrict__ Alo,
                 const __nv_bfloat16* __restrict__ Whi, const __nv_bfloat16* __restrict__ Wlo,
                 const float* __restrict__ bias, float* __restrict__ C) {
    extern __shared__ char smem[];
    uint32_t sbase = smem_u32(smem);
    int tid = threadIdx.x, wid = tid >> 5, lane = tid & 31;
    size_t m0 = (size_t)blockIdx.y * 128, n0 = (size_t)blockIdx.x * 128;
    int wm = wid & 1, wn = wid >> 1;   // 2 warps along M, 4 along N

    float acc[4][4][4];
#pragma unroll
    for (int i = 0; i < 4; i++)
#pragma unroll
        for (int j = 0; j < 4; j++)
#pragma unroll
            for (int k = 0; k < 4; k++) acc[i][j][k] = 0.0f;

    load_stage(sbase, 0, Ahi, Alo, Whi, Wlo, m0, n0, 0, tid);
    CP_COMMIT();

    const int NCHUNK = Dd / 32;   // 64
    for (int c = 0; c < NCHUNK; c++) {
        CP_WAIT0();
        __syncthreads();
        if (c + 1 < NCHUNK) {
            load_stage(sbase, (c + 1) & 1, Ahi, Alo, Whi, Wlo, m0, n0, c + 1, tid);
            CP_COMMIT();
        }
        uint32_t stg = sbase + (uint32_t)(c & 1) * STAGE_BYTES;
        uint32_t aB = stg + (uint32_t)(wm * 64 + (lane & 15)) * PITCH;
        uint32_t wB = stg + 2 * TILE_BYTES + (uint32_t)(wn * 32 + (lane & 15)) * PITCH;
#pragma unroll
        for (int ks = 0; ks < 2; ks++) {
            uint32_t qb = (uint32_t)(2 * ks + (lane >> 4)) * 16;
            uint32_t ah[4][4], al[4][4], wh[2][4], wl[2][4];
#pragma unroll
            for (int mi = 0; mi < 4; mi++) ldsm4(ah[mi], aB + mi * 16 * PITCH + qb);
#pragma unroll
            for (int mi = 0; mi < 4; mi++) ldsm4(al[mi], aB + TILE_BYTES + mi * 16 * PITCH + qb);
#pragma unroll
            for (int ni = 0; ni < 2; ni++) ldsm4(wh[ni], wB + ni * 16 * PITCH + qb);
#pragma unroll
            for (int ni = 0; ni < 2; ni++) ldsm4(wl[ni], wB + TILE_BYTES + ni * 16 * PITCH + qb);
#pragma unroll
            for (int mi = 0; mi < 4; mi++) {
#pragma unroll
                for (int nj = 0; nj < 4; nj++) {
                    int ni = nj >> 1, sub = nj & 1;
                    mma16816(acc[mi][nj], ah[mi], wh[ni][sub], wh[ni][sub + 2]);
                    mma16816(acc[mi][nj], ah[mi], wl[ni][sub], wl[ni][sub + 2]);
                    mma16816(acc[mi][nj], al[mi], wh[ni][sub], wh[ni][sub + 2]);
                }
            }
        }
    }

    // epilogue: c0,c1 -> (row, col..col+1), c2,c3 -> (row+8, col..col+1)
    int r0 = lane >> 2, cg = (lane & 3) * 2;
#pragma unroll
    for (int mi = 0; mi < 4; mi++) {
        size_t row = m0 + wm * 64 + mi * 16 + r0;
#pragma unroll
        for (int nj = 0; nj < 4; nj++) {
            size_t col = n0 + wn * 32 + nj * 8 + cg;
            float b0 = bias[col], b1 = bias[col + 1];
            float2 o0, o1;
            o0.x = acc[mi][nj][0] + b0; o0.y = acc[mi][nj][1] + b1;
            o1.x = acc[mi][nj][2] + b0; o1.y = acc[mi][nj][3] + b1;
            *(float2*)(C + row * Dd + col) = o0;
            *(float2*)(C + (row + 8) * Dd + col) = o1;
        }
    }
}

// ---------------- attention over S=16 slots; q -> ctx in place ----------------
__global__ void attn_kernel() {
    __shared__ float skk[Sn * HDi];
    __shared__ float svv[Sn * HDi];
    int chunk = blockIdx.x, h = blockIdx.y, b = blockIdx.z;
    int tid = threadIdx.x;
    for (int i = tid; i < Sn * HDi; i += 256) {
        int s = i >> 6, d = i & 63;
        size_t off = ((size_t)(b * Sn + s)) * Dd + h * HDi + d;
        skk[i] = g_kk[off];
        svv[i] = g_vv[off];
    }
    __syncthreads();
    int warp = tid >> 5, lane = tid & 31;
    for (int t = 0; t < 16; t++) {
        int l = chunk * 128 + warp * 16 + t;
        float* qp = g_q + ((size_t)b * Lq + l) * Dd + h * HDi;
        float q0 = qp[lane], q1 = qp[lane + 32];
        float e[16];
        float m = -1e30f;
#pragma unroll
        for (int s = 0; s < Sn; s++) {
            float p = q0 * skk[s * 64 + lane] + q1 * skk[s * 64 + lane + 32];
#pragma unroll
            for (int o = 16; o; o >>= 1) p += __shfl_xor_sync(0xffffffffu, p, o);
            p *= 0.125f;
            e[s] = p;
            m = fmaxf(m, p);
        }
        float sum = 0.0f;
#pragma unroll
        for (int s = 0; s < Sn; s++) { e[s] = __expf(e[s] - m); sum += e[s]; }
        float inv = 1.0f / sum;
        float c0 = 0.0f, c1 = 0.0f;
#pragma unroll
        for (int s = 0; s < Sn; s++) {
            c0 += e[s] * svv[s * 64 + lane];
            c1 += e[s] * svv[s * 64 + lane + 32];
        }
        qp[lane] = c0 * inv;
        qp[lane + 32] = c1 * inv;
    }
}

// ---------------- x = RMS(x + x_b, post_w) in place ----------------
__global__ void resid_rms_kernel(float* __restrict__ x, const float* __restrict__ post_w) {
    int r = blockIdx.x;
    __shared__ float srow[Dd];
    float* xr = x + (size_t)r * Dd;
    const float* br = g_xb + (size_t)r * Dd;
    float ss = 0.0f;
    for (int i = threadIdx.x; i < Dd; i += 256) {
        float v = xr[i] + br[i];
        srow[i] = v;
        ss += v * v;
    }
    ss = block_sum256(ss);
    float inv = rsqrtf(ss * (1.0f / Dd) + EPSv);
    for (int i = threadIdx.x; i < Dd; i += 256) xr[i] = srow[i] * inv * post_w[i];
}

// ---------------- host orchestration ----------------
extern "C" void kernel_launch(void* const* d_in, const int* in_sizes, int n_in,
                              void* d_out, int out_size) {
    const float* x_in       = (const float*)d_in[0];
    const float* ws0        = (const float*)d_in[1];
    const float* compete_w  = (const float*)d_in[2];
    const float* compete_b  = (const float*)d_in[3];
    const float* write_w    = (const float*)d_in[4];
    const float* write_b    = (const float*)d_in[5];
    const float* in_proj_w  = (const float*)d_in[6];
    const float* in_proj_b  = (const float*)d_in[7];
    const float* out_proj_w = (const float*)d_in[8];
    const float* out_proj_b = (const float*)d_in[9];
    // d_in[10], d_in[11]: ig_w/ig_b — dead code in reference
    const float* pre_w      = (const float*)d_in[12];
    const float* post_w     = (const float*)d_in[13];
    float* x = (float*)d_out;

    static float* p_q = nullptr;
    static float* p_xb = nullptr;
    static __nv_bfloat16 *p_ahi, *p_alo, *p_wqhi, *p_wqlo, *p_wohi, *p_wolo;
    if (!p_q) {
        void* t;
        cudaGetSymbolAddress(&t, g_q);    p_q    = (float*)t;
        cudaGetSymbolAddress(&t, g_xb);   p_xb   = (float*)t;
        cudaGetSymbolAddress(&t, g_ahi);  p_ahi  = (__nv_bfloat16*)t;
        cudaGetSymbolAddress(&t, g_alo);  p_alo  = (__nv_bfloat16*)t;
        cudaGetSymbolAddress(&t, g_wqhi); p_wqhi = (__nv_bfloat16*)t;
        cudaGetSymbolAddress(&t, g_wqlo); p_wqlo = (__nv_bfloat16*)t;
        cudaGetSymbolAddress(&t, g_wohi); p_wohi = (__nv_bfloat16*)t;
        cudaGetSymbolAddress(&t, g_wolo); p_wolo = (__nv_bfloat16*)t;
        cudaFuncSetAttribute(gemm_bf16_kernel,
                             cudaFuncAttributeMaxDynamicSharedMemorySize, HSMEM);
    }

    const int n4_x = (Bq * Lq * Dd) / 4;
    const int n4_w = (Dd * Dd) / 4;

    cudaMemcpyAsync(x, x_in, sizeof(float) * (size_t)Bq * Lq * Dd, cudaMemcpyDeviceToDevice);
    init_ws_kernel<<<(Bq * Sn * Dd + 255) / 256, 256>>>(ws0);

    // convert weights once per launch
    conv_split_kernel<<<n4_w / 256, 256>>>(in_proj_w, p_wqhi, p_wqlo, n4_w);
    conv_split_kernel<<<n4_w / 256, 256>>>(out_proj_w, p_wohi, p_wolo, n4_w);

    for (int it = 0; it < NBi; ++it) {
        rms_logits_kernel<<<Bq * Lq, 256>>>(x, pre_w, compete_w, compete_b);
        topk_xc_kernel<<<Bq * Sn, 256>>>(x);
        gemm_small_split<<<dim3(Dd / 64, 4, KS), 256>>>(0, write_w);
        gemm_small_reduce<<<dim3(64 * Dd / 256, 1), 256>>>(0, write_b);
        ws_update_kernel<<<Bq * Sn, 256>>>(post_w);
        gemm_small_split<<<dim3(Dd / 64, 4, KS * 2), 256>>>(1, in_proj_w + (size_t)Dd * Dd);
        gemm_small_reduce<<<dim3(64 * Dd / 256, 2), 256>>>(1, in_proj_b + Dd);
        // q = x @ wq.T + bq  (HMMA bf16x3)
        conv_split_kernel<<<n4_x / 256, 256>>>(x, p_ahi, p_alo, n4_x);
        gemm_bf16_kernel<<<dim3(Dd / 128, (Bq * Lq) / 128), 256, HSMEM>>>(
            p_ahi, p_alo, p_wqhi, p_wqlo, in_proj_b, p_q);
        attn_kernel<<<dim3(Lq / 128, Hn, Bq), 256>>>();
        // x_b = ctx @ out_proj_w.T + out_proj_b  (HMMA bf16x3)
        conv_split_kernel<<<n4_x / 256, 256>>>(p_q, p_ahi, p_alo, n4_x);
        gemm_bf16_kernel<<<dim3(Dd / 128, (Bq * Lq) / 128), 256, HSMEM>>>(
            p_ahi, p_alo, p_wohi, p_wolo, out_proj_b, p_xb);
        resid_rms_kernel<<<Bq * Lq, 256>>>(x, post_w);
    }
}

// round 5
// speedup vs baseline: 5.3900x; 2.5040x over previous
#include <cuda_runtime.h>
#include <cuda_bf16.h>
#include <math.h>
#include <stdint.h>

// Shapes (static)
#define Bq 4
#define Lq 2048
#define Dd 2048
#define Sn 16
#define NBi 2
#define Hn 32
#define HDi 64
#define SH 512            // Sn * Hn
#define EPSv 1e-6f
#define KS 4              // split-K factor for small GEMMs

// ---------------- scratch (device globals; no allocation) ----------------
__device__ float g_xb[(size_t)Bq * Lq * Dd];     // out-proj result (64 MB)
__device__ float g_sc[(size_t)Bq * Lq * SH];     // attention scores (16 MB)
__device__ float g_logits[(size_t)Bq * Sn * Lq];
__device__ float g_xc[(size_t)Bq * Sn * Dd];
__device__ float g_ws[(size_t)Bq * Sn * Dd];
__device__ float g_wr[(size_t)Bq * Sn * Dd];
__device__ float g_kk[(size_t)Bq * Sn * Dd];
__device__ float g_vv[(size_t)Bq * Sn * Dd];
__device__ float g_part[2][KS][64 * Dd];
__device__ float g_sb[Bq * SH];                  // per-(b,j) score bias = bq . kk

// bf16 hi/lo split operands
__device__ __align__(128) __nv_bfloat16 g_ahi[(size_t)Bq * Lq * Dd];   // x hi
__device__ __align__(128) __nv_bfloat16 g_alo[(size_t)Bq * Lq * Dd];   // x lo
__device__ __align__(128) __nv_bfloat16 g_uhi[(size_t)Bq * SH * Dd];   // u = kk.wq
__device__ __align__(128) __nv_bfloat16 g_ulo[(size_t)Bq * SH * Dd];
__device__ __align__(128) __nv_bfloat16 g_zthi[(size_t)Bq * Dd * SH];  // zt = Wo.vv
__device__ __align__(128) __nv_bfloat16 g_ztlo[(size_t)Bq * Dd * SH];
__device__ __align__(128) __nv_bfloat16 g_athi[(size_t)Bq * Lq * SH];  // att weights
__device__ __align__(128) __nv_bfloat16 g_atlo[(size_t)Bq * Lq * SH];

// ---------------- PTX helpers (sm_80-compatible) ----------------
__device__ __forceinline__ uint32_t smem_u32(const void* p) {
    return (uint32_t)__cvta_generic_to_shared(p);
}

__device__ __forceinline__ void cpasync16(uint32_t dst, const void* src) {
    asm volatile("cp.async.cg.shared.global [%0], [%1], 16;\n" :: "r"(dst), "l"(src));
}
#define CP_COMMIT() asm volatile("cp.async.commit_group;\n" ::: "memory")
#define CP_WAIT0()  asm volatile("cp.async.wait_group 0;\n" ::: "memory")

__device__ __forceinline__ void ldsm4(uint32_t* r, uint32_t addr) {
    asm volatile("ldmatrix.sync.aligned.m8n8.x4.shared.b16 {%0,%1,%2,%3}, [%4];\n"
                 : "=r"(r[0]), "=r"(r[1]), "=r"(r[2]), "=r"(r[3]) : "r"(addr));
}

__device__ __forceinline__ void mma16816(float* c, const uint32_t* a, uint32_t b0, uint32_t b1) {
    asm volatile(
        "mma.sync.aligned.m16n8k16.row.col.f32.bf16.bf16.f32 "
        "{%0,%1,%2,%3}, {%4,%5,%6,%7}, {%8,%9}, {%0,%1,%2,%3};\n"
        : "+f"(c[0]), "+f"(c[1]), "+f"(c[2]), "+f"(c[3])
        : "r"(a[0]), "r"(a[1]), "r"(a[2]), "r"(a[3]), "r"(b0), "r"(b1));
}

// ---------------- generic helpers ----------------
__device__ __forceinline__ float warp_sum(float v) {
#pragma unroll
    for (int o = 16; o; o >>= 1) v += __shfl_xor_sync(0xffffffffu, v, o);
    return v;
}

__device__ __forceinline__ float block_sum256(float v) {
    __shared__ float red[8];
    int lane = threadIdx.x & 31, warp = threadIdx.x >> 5;
    v = warp_sum(v);
    if (lane == 0) red[warp] = v;
    __syncthreads();
    if (warp == 0) {
        float r = (lane < 8) ? red[lane] : 0.0f;
        r = warp_sum(r);
        if (lane == 0) red[0] = r;
    }
    __syncthreads();
    float out = red[0];
    __syncthreads();
    return out;
}

__device__ __forceinline__ void split_store(float v, __nv_bfloat16* hi, __nv_bfloat16* lo) {
    __nv_bfloat16 h = __float2bfloat16(v);
    *hi = h;
    *lo = __float2bfloat16(v - __bfloat162float(h));
}

// ---------------- init ----------------
__global__ void init_ws_kernel(const float* __restrict__ ws0) {
    int i = blockIdx.x * 256 + threadIdx.x;
    if (i < Bq * Sn * Dd) g_ws[i] = ws0[i & (Sn * Dd - 1)];
}

// copy x to d_out AND emit bf16 hi/lo
__global__ void copy_split_kernel(const float* __restrict__ src, float* __restrict__ dstx,
                                  __nv_bfloat16* __restrict__ hi, __nv_bfloat16* __restrict__ lo,
                                  int n4) {
    int i = blockIdx.x * 256 + threadIdx.x;
    if (i >= n4) return;
    float4 f = ((const float4*)src)[i];
    ((float4*)dstx)[i] = f;
    __nv_bfloat162 h01 = __floats2bfloat162_rn(f.x, f.y);
    __nv_bfloat162 h23 = __floats2bfloat162_rn(f.z, f.w);
    float2 hf01 = __bfloat1622float2(h01);
    float2 hf23 = __bfloat1622float2(h23);
    __nv_bfloat162 l01 = __floats2bfloat162_rn(f.x - hf01.x, f.y - hf01.y);
    __nv_bfloat162 l23 = __floats2bfloat162_rn(f.z - hf23.x, f.w - hf23.y);
    uint2 hv, lv;
    hv.x = *(uint32_t*)&h01; hv.y = *(uint32_t*)&h23;
    lv.x = *(uint32_t*)&l01; lv.y = *(uint32_t*)&l23;
    ((uint2*)hi)[i] = hv;
    ((uint2*)lo)[i] = lv;
}

// ---------------- fused RMS(x)*pre_w @ compete_w.T + compete_b ----------------
// 16 concurrent slot accumulators per thread: one pass over x, 17 FMAs/element.
__global__ void rms_logits_kernel(const float* __restrict__ x,
                                  const float* __restrict__ pre_w,
                                  const float* __restrict__ cw,
                                  const float* __restrict__ cb) {
    __shared__ float sd[16][256];
    int row = blockIdx.x;
    const float* xr = x + (size_t)row * Dd;
    float acc[16];
#pragma unroll
    for (int s = 0; s < 16; s++) acc[s] = 0.0f;
    float ss = 0.0f;
    for (int i = threadIdx.x; i < Dd; i += 256) {
        float v = xr[i];
        ss += v * v;
        float xp = v * pre_w[i];
#pragma unroll
        for (int s = 0; s < 16; s++) acc[s] += xp * cw[s * Dd + i];
    }
#pragma unroll
    for (int s = 0; s < 16; s++) sd[s][threadIdx.x] = acc[s];
    ss = block_sum256(ss);   // barriers inside also publish sd
    float inv = rsqrtf(ss * (1.0f / Dd) + EPSv);
    int warp = threadIdx.x >> 5, lane = threadIdx.x & 31;
    int b = row / Lq, l = row % Lq;
#pragma unroll
    for (int k = 0; k < 2; k++) {
        int s = warp * 2 + k;
        float d = 0.0f;
#pragma unroll
        for (int j = 0; j < 8; j++) d += sd[s][lane + j * 32];
        d = warp_sum(d);
        if (lane == 0) g_logits[((size_t)(b * Sn + s)) * Lq + l] = d * inv + cb[s];
    }
}

// ---------------- top-4 per (b,slot) + softmax + weighted x-combo ----------------
__device__ __forceinline__ bool tk_better(float v1, int i1, float v2, int i2) {
    return (v1 > v2) || (v1 == v2 && i1 < i2);
}

__global__ void topk_xc_kernel(const float* __restrict__ x) {
    int bs = blockIdx.x;
    int b = bs / Sn;
    const float* lg = g_logits + (size_t)bs * Lq;
    float lv[4] = {-3.402823466e38f, -3.402823466e38f, -3.402823466e38f, -3.402823466e38f};
    int li[4] = {0x7fffffff, 0x7fffffff, 0x7fffffff, 0x7fffffff};
    for (int l = threadIdx.x; l < Lq; l += 256) {
        float v = lg[l];
        if (tk_better(v, l, lv[3], li[3])) {
            lv[3] = v; li[3] = l;
#pragma unroll
            for (int k = 3; k > 0; --k) {
                if (tk_better(lv[k], li[k], lv[k - 1], li[k - 1])) {
                    float tv = lv[k]; lv[k] = lv[k - 1]; lv[k - 1] = tv;
                    int ti = li[k]; li[k] = li[k - 1]; li[k - 1] = ti;
                }
            }
        }
    }
    __shared__ float sv[256 * 4];
    __shared__ int si[256 * 4];
#pragma unroll
    for (int k = 0; k < 4; k++) { sv[threadIdx.x * 4 + k] = lv[k]; si[threadIdx.x * 4 + k] = li[k]; }
    for (int off = 128; off >= 1; off >>= 1) {
        __syncthreads();
        if (threadIdx.x < off) {
            float av[4], bv[4]; int ai[4], bi[4];
#pragma unroll
            for (int k = 0; k < 4; k++) {
                av[k] = sv[threadIdx.x * 4 + k]; ai[k] = si[threadIdx.x * 4 + k];
                bv[k] = sv[(threadIdx.x + off) * 4 + k]; bi[k] = si[(threadIdx.x + off) * 4 + k];
            }
            float ov[4]; int oi[4];
            int ia = 0, ib = 0;
#pragma unroll
            for (int k = 0; k < 4; k++) {
                bool ta = (ib >= 4) || (ia < 4 && tk_better(av[ia], ai[ia], bv[ib], bi[ib]));
                if (ta) { ov[k] = av[ia]; oi[k] = ai[ia]; ia++; }
                else    { ov[k] = bv[ib]; oi[k] = bi[ib]; ib++; }
            }
#pragma unroll
            for (int k = 0; k < 4; k++) { sv[threadIdx.x * 4 + k] = ov[k]; si[threadIdx.x * 4 + k] = oi[k]; }
        }
    }
    __syncthreads();
    __shared__ float swgt[4];
    __shared__ int sidx[4];
    if (threadIdx.x == 0) {
        float m = sv[0];
        float e[4], sum = 0.0f;
#pragma unroll
        for (int k = 0; k < 4; k++) { e[k] = expf(sv[k] - m); sum += e[k]; }
#pragma unroll
        for (int k = 0; k < 4; k++) { swgt[k] = e[k] / sum; sidx[k] = si[k]; }
    }
    __syncthreads();
    float w0 = swgt[0], w1 = swgt[1], w2 = swgt[2], w3 = swgt[3];
    const float* x0 = x + ((size_t)b * Lq + sidx[0]) * Dd;
    const float* x1 = x + ((size_t)b * Lq + sidx[1]) * Dd;
    const float* x2 = x + ((size_t)b * Lq + sidx[2]) * Dd;
    const float* x3 = x + ((size_t)b * Lq + sidx[3]) * Dd;
    float* xc = g_xc + (size_t)bs * Dd;
    for (int d = threadIdx.x; d < Dd; d += 256)
        xc[d] = w0 * x0[d] + w1 * x1[d] + w2 * x2[d] + w3 * x3[d];
}

// ---------------- small GEMM, split-K ----------------
__global__ void gemm_small_split(int which, const float* __restrict__ Wbase) {
    int z = blockIdx.z;
    int zi = z / KS, kz = z % KS;
    const float* A = (which == 0) ? g_xc : g_ws;
    const float* W = Wbase + (size_t)zi * Dd * Dd;
    __shared__ float As[16][65];
    __shared__ float Ws[64][65];
    int n0 = blockIdx.x * 64, m0 = blockIdx.y * 16;
    int tid = threadIdx.x;
    int ar = tid >> 4, ac = (tid & 15) * 4;
    int tx = tid & 63, ty = tid >> 6;
    float acc[4] = {0, 0, 0, 0};
    int kbeg = kz * (Dd / KS), kend = kbeg + Dd / KS;
    for (int k0 = kbeg; k0 < kend; k0 += 64) {
        float4 a = *(const float4*)(A + (size_t)(m0 + ar) * Dd + k0 + ac);
        As[ar][ac + 0] = a.x; As[ar][ac + 1] = a.y; As[ar][ac + 2] = a.z; As[ar][ac + 3] = a.w;
#pragma unroll
        for (int q = 0; q < 4; q++) {
            int wr = ar + q * 16;
            float4 w = *(const float4*)(W + (size_t)(n0 + wr) * Dd + k0 + ac);
            Ws[ac + 0][wr] = w.x; Ws[ac + 1][wr] = w.y; Ws[ac + 2][wr] = w.z; Ws[ac + 3][wr] = w.w;
        }
        __syncthreads();
#pragma unroll
        for (int k = 0; k < 64; k++) {
            float wv = Ws[k][tx];
#pragma unroll
            for (int i = 0; i < 4; i++) acc[i] += As[ty * 4 + i][k] * wv;
        }
        __syncthreads();
    }
    float* P = g_part[zi][kz];
#pragma unroll
    for (int i = 0; i < 4; i++)
        P[(size_t)(m0 + ty * 4 + i) * Dd + n0 + tx] = acc[i];
}

__global__ void gemm_small_reduce(int which, const float* __restrict__ bias) {
    int zi = blockIdx.y;
    int i = blockIdx.x * 256 + threadIdx.x;
    float s = g_part[zi][0][i] + g_part[zi][1][i] + g_part[zi][2][i] + g_part[zi][3][i];
    s += bias[(size_t)zi * Dd + (i & (Dd - 1))];
    float* C = (which == 0) ? g_wr : (zi == 0 ? g_kk : g_vv);
    C[i] = s;
}

// ---------------- ws = RMS(ws + written, post_w) in place ----------------
__global__ void ws_update_kernel(const float* __restrict__ post_w) {
    int r = blockIdx.x;
    __shared__ float srow[Dd];
    float* wsr = g_ws + (size_t)r * Dd;
    const float* wrr = g_wr + (size_t)r * Dd;
    float ss = 0.0f;
    for (int i = threadIdx.x; i < Dd; i += 256) {
        float v = wsr[i] + wrr[i];
        srow[i] = v;
        ss += v * v;
    }
    ss = block_sum256(ss);
    float inv = rsqrtf(ss * (1.0f / Dd) + EPSv);
    for (int i = threadIdx.x; i < Dd; i += 256) wsr[i] = srow[i] * inv * post_w[i];
}

// ---------------- u build: u[b,(h,s),n] = sum_d kk[b,s,h64+d] * wq[h64+d,n]; sb = bq.kk ----------------
// grid (Dd/128, Hn, Bq), 256 threads
__global__ void u_build_kernel(const float* __restrict__ wq, const float* __restrict__ bq) {
    __shared__ float swq[64][128];
    __shared__ float skk[16][64];
    int n0 = blockIdx.x * 128, h = blockIdx.y, b = blockIdx.z;
    int tid = threadIdx.x;
#pragma unroll
    for (int rep = 0; rep < 8; rep++) {
        int e = tid * 4 + rep * 1024;
        int d = e >> 7, n = e & 127;
        float4 w = *(const float4*)(wq + (size_t)(h * 64 + d) * Dd + n0 + n);
        swq[d][n + 0] = w.x; swq[d][n + 1] = w.y; swq[d][n + 2] = w.z; swq[d][n + 3] = w.w;
    }
    {
        int e = tid * 4;
        int s = e >> 6, d = e & 63;
        float4 k4 = *(const float4*)(g_kk + ((size_t)(b * Sn + s)) * Dd + h * 64 + d);
        skk[s][d + 0] = k4.x; skk[s][d + 1] = k4.y; skk[s][d + 2] = k4.z; skk[s][d + 3] = k4.w;
    }
    __syncthreads();
    int nn = tid & 127, sh = tid >> 7;
    float acc[8];
#pragma unroll
    for (int k = 0; k < 8; k++) acc[k] = 0.0f;
    for (int d = 0; d < 64; d++) {
        float w = swq[d][nn];
#pragma unroll
        for (int k = 0; k < 8; k++) acc[k] += skk[sh * 8 + k][d] * w;
    }
#pragma unroll
    for (int k = 0; k < 8; k++) {
        int j = h * 16 + sh * 8 + k;
        size_t idx = ((size_t)(b * SH + j)) * Dd + n0 + nn;
        split_store(acc[k], g_uhi + idx, g_ulo + idx);
    }
    if (blockIdx.x == 0 && tid < 16) {
        float a = 0.0f;
        for (int d = 0; d < 64; d++) a += bq[h * 64 + d] * skk[tid][d];
        g_sb[b * SH + h * 16 + tid] = a;
    }
}

// ---------------- zt build: zt[b,n,(h,s)] = sum_d vv[b,s,h64+d] * Wo[n,h64+d] ----------------
// grid (Dd/64, Hn, Bq), 256 threads
__global__ void z_build_kernel(const float* __restrict__ Wo) {
    __shared__ float swo[64][65];
    __shared__ float svv[16][64];
    int n0 = blockIdx.x * 64, h = blockIdx.y, b = blockIdx.z;
    int tid = threadIdx.x;
#pragma unroll
    for (int rep = 0; rep < 4; rep++) {
        int e = tid * 4 + rep * 1024;
        int n = e >> 6, d = e & 63;
        float4 w = *(const float4*)(Wo + (size_t)(n0 + n) * Dd + h * 64 + d);
        swo[n][d + 0] = w.x; swo[n][d + 1] = w.y; swo[n][d + 2] = w.z; swo[n][d + 3] = w.w;
    }
    {
        int e = tid * 4;
        int s = e >> 6, d = e & 63;
        float4 v4 = *(const float4*)(g_vv + ((size_t)(b * Sn + s)) * Dd + h * 64 + d);
        svv[s][d + 0] = v4.x; svv[s][d + 1] = v4.y; svv[s][d + 2] = v4.z; svv[s][d + 3] = v4.w;
    }
    __syncthreads();
    int n = tid & 63, sq = tid >> 6;
    float acc[4];
#pragma unroll
    for (int k = 0; k < 4; k++) acc[k] = 0.0f;
    for (int d = 0; d < 64; d++) {
        float w = swo[n][d];
#pragma unroll
        for (int k = 0; k < 4; k++) acc[k] += svv[sq * 4 + k][d] * w;
    }
#pragma unroll
    for (int k = 0; k < 4; k++) {
        int j = h * 16 + sq * 4 + k;
        size_t idx = ((size_t)(b * Dd + n0 + n)) * SH + j;
        split_store(acc[k], g_zthi + idx, g_ztlo + idx);
    }
}

// ---------------- HMMA bf16x3 GEMM: C[z][M,N] = A[z] @ W[z]^T + bias[z] ----------------
// CTA 128x128, 8 warps, K-chunks of 32, 2-stage cp.async double buffer. Runtime K/ldc/strides.
#define PITCH 80
#define TILE_BYTES (128 * PITCH)
#define STAGE_BYTES (4 * TILE_BYTES)
#define HSMEM (2 * STAGE_BYTES)

static __device__ __forceinline__ void load_stage(
        uint32_t sbase, int stage,
        const __nv_bfloat16* __restrict__ Ahi, const __nv_bfloat16* __restrict__ Alo,
        const __nv_bfloat16* __restrict__ Whi, const __nv_bfloat16* __restrict__ Wlo,
        size_t m0, size_t n0, int c, int tid, int K) {
    uint32_t st = sbase + (uint32_t)stage * STAGE_BYTES;
    int kb = c * 32;
#pragma unroll
    for (int h = 0; h < 2; h++) {
        int e = tid + h * 256;
        int row = e >> 2, q = e & 3;
        uint32_t so = (uint32_t)row * PITCH + (uint32_t)q * 16;
        size_t goff = (size_t)row * K + kb + q * 8;
        cpasync16(st + so,                  Ahi + (m0 * K + goff));
        cpasync16(st + TILE_BYTES + so,     Alo + (m0 * K + goff));
        cpasync16(st + 2 * TILE_BYTES + so, Whi + (n0 * K + goff));
        cpasync16(st + 3 * TILE_BYTES + so, Wlo + (n0 * K + goff));
    }
}

__global__ void __launch_bounds__(256, 1)
gemm_bf16_kernel(const __nv_bfloat16* __restrict__ Ahi, const __nv_bfloat16* __restrict__ Alo,
                 const __nv_bfloat16* __restrict__ Whi, const __nv_bfloat16* __restrict__ Wlo,
                 const float* __restrict__ bias, float* __restrict__ C,
                 int K, int ldc, size_t sA, size_t sW, size_t sC, int sBias) {
    extern __shared__ char smem[];
    uint32_t sbase = smem_u32(smem);
    int z = blockIdx.z;
    Ahi += (size_t)z * sA; Alo += (size_t)z * sA;
    Whi += (size_t)z * sW; Wlo += (size_t)z * sW;
    C   += (size_t)z * sC; bias += (size_t)z * sBias;
    int tid = threadIdx.x, wid = tid >> 5, lane = tid & 31;
    size_t m0 = (size_t)blockIdx.y * 128, n0 = (size_t)blockIdx.x * 128;
    int wm = wid & 1, wn = wid >> 1;

    float acc[4][4][4];
#pragma unroll
    for (int i = 0; i < 4; i++)
#pragma unroll
        for (int j = 0; j < 4; j++)
#pragma unroll
            for (int k = 0; k < 4; k++) acc[i][j][k] = 0.0f;

    load_stage(sbase, 0, Ahi, Alo, Whi, Wlo, m0, n0, 0, tid, K);
    CP_COMMIT();

    const int NCHUNK = K / 32;
    for (int c = 0; c < NCHUNK; c++) {
        CP_WAIT0();
        __syncthreads();
        if (c + 1 < NCHUNK) {
            load_stage(sbase, (c + 1) & 1, Ahi, Alo, Whi, Wlo, m0, n0, c + 1, tid, K);
            CP_COMMIT();
        }
        uint32_t stg = sbase + (uint32_t)(c & 1) * STAGE_BYTES;
        uint32_t aB = stg + (uint32_t)(wm * 64 + (lane & 15)) * PITCH;
        uint32_t wB = stg + 2 * TILE_BYTES + (uint32_t)(wn * 32 + (lane & 15)) * PITCH;
#pragma unroll
        for (int ks = 0; ks < 2; ks++) {
            uint32_t qb = (uint32_t)(2 * ks + (lane >> 4)) * 16;
            uint32_t ah[4][4], al[4][4], wh[2][4], wl[2][4];
#pragma unroll
            for (int mi = 0; mi < 4; mi++) ldsm4(ah[mi], aB + mi * 16 * PITCH + qb);
#pragma unroll
            for (int mi = 0; mi < 4; mi++) ldsm4(al[mi], aB + TILE_BYTES + mi * 16 * PITCH + qb);
#pragma unroll
            for (int ni = 0; ni < 2; ni++) ldsm4(wh[ni], wB + ni * 16 * PITCH + qb);
#pragma unroll
            for (int ni = 0; ni < 2; ni++) ldsm4(wl[ni], wB + TILE_BYTES + ni * 16 * PITCH + qb);
#pragma unroll
            for (int mi = 0; mi < 4; mi++) {
#pragma unroll
                for (int nj = 0; nj < 4; nj++) {
                    int ni = nj >> 1, sub = nj & 1;
                    mma16816(acc[mi][nj], ah[mi], wh[ni][sub], wh[ni][sub + 2]);
                    mma16816(acc[mi][nj], ah[mi], wl[ni][sub], wl[ni][sub + 2]);
                    mma16816(acc[mi][nj], al[mi], wh[ni][sub], wh[ni][sub + 2]);
                }
            }
        }
    }

    int r0 = lane >> 2, cg = (lane & 3) * 2;
#pragma unroll
    for (int mi = 0; mi < 4; mi++) {
        size_t row = m0 + wm * 64 + mi * 16 + r0;
#pragma unroll
        for (int nj = 0; nj < 4; nj++) {
            size_t col = n0 + wn * 32 + nj * 8 + cg;
            float b0 = bias[col], b1 = bias[col + 1];
            float2 o0, o1;
            o0.x = acc[mi][nj][0] + b0; o0.y = acc[mi][nj][1] + b1;
            o1.x = acc[mi][nj][2] + b0; o1.y = acc[mi][nj][3] + b1;
            *(float2*)(C + row * ldc + col) = o0;
            *(float2*)(C + (row + 8) * ldc + col) = o1;
        }
    }
}

// ---------------- attention softmax: 32 groups of 16 per row; writes att hi/lo ----------------
// grid = Bq*Lq rows, 256 threads (2 values per thread)
__global__ void attn_softmax_kernel() {
    int row = blockIdx.x;
    int t = threadIdx.x;
    const float* sr = g_sc + (size_t)row * SH;
    float v0 = sr[2 * t]     * 0.125f;
    float v1 = sr[2 * t + 1] * 0.125f;
    float m = fmaxf(v0, v1);
#pragma unroll
    for (int o = 1; o <= 4; o <<= 1) m = fmaxf(m, __shfl_xor_sync(0xffffffffu, m, o));
    float e0 = __expf(v0 - m), e1 = __expf(v1 - m);
    float s = e0 + e1;
#pragma unroll
    for (int o = 1; o <= 4; o <<= 1) s += __shfl_xor_sync(0xffffffffu, s, o);
    float inv = 1.0f / s;
    float a0 = e0 * inv, a1 = e1 * inv;
    __nv_bfloat162 h = __floats2bfloat162_rn(a0, a1);
    float2 hf = __bfloat1622float2(h);
    __nv_bfloat162 lo = __floats2bfloat162_rn(a0 - hf.x, a1 - hf.y);
    ((uint32_t*)(g_athi + (size_t)row * SH))[t] = *(uint32_t*)&h;
    ((uint32_t*)(g_atlo + (size_t)row * SH))[t] = *(uint32_t*)&lo;
}

// ---------------- x = RMS(x + x_b, post_w) in place; also emits x hi/lo ----------------
__global__ void resid_rms_kernel(float* __restrict__ x, const float* __restrict__ post_w) {
    int r = blockIdx.x;
    __shared__ float srow[Dd];
    float* xr = x + (size_t)r * Dd;
    const float* br = g_xb + (size_t)r * Dd;
    float ss = 0.0f;
    for (int i = threadIdx.x; i < Dd; i += 256) {
        float v = xr[i] + br[i];
        srow[i] = v;
        ss += v * v;
    }
    ss = block_sum256(ss);
    float inv = rsqrtf(ss * (1.0f / Dd) + EPSv);
    for (int i = threadIdx.x; i < Dd; i += 256) {
        float o = srow[i] * inv * post_w[i];
        xr[i] = o;
        size_t idx = (size_t)r * Dd + i;
        split_store(o, g_ahi + idx, g_alo + idx);
    }
}

// ---------------- host orchestration ----------------
extern "C" void kernel_launch(void* const* d_in, const int* in_sizes, int n_in,
                              void* d_out, int out_size) {
    const float* x_in       = (const float*)d_in[0];
    const float* ws0        = (const float*)d_in[1];
    const float* compete_w  = (const float*)d_in[2];
    const float* compete_b  = (const float*)d_in[3];
    const float* write_w    = (const float*)d_in[4];
    const float* write_b    = (const float*)d_in[5];
    const float* in_proj_w  = (const float*)d_in[6];
    const float* in_proj_b  = (const float*)d_in[7];
    const float* out_proj_w = (const float*)d_in[8];
    const float* out_proj_b = (const float*)d_in[9];
    // d_in[10], d_in[11]: ig_w/ig_b — dead code in reference
    const float* pre_w      = (const float*)d_in[12];
    const float* post_w     = (const float*)d_in[13];
    float* x = (float*)d_out;

    static float* p_xb = nullptr;
    static float* p_sc;
    static float* p_sb;
    static __nv_bfloat16 *p_ahi, *p_alo, *p_uhi, *p_ulo, *p_zthi, *p_ztlo, *p_athi, *p_atlo;
    if (!p_xb) {
        void* t;
        cudaGetSymbolAddress(&t, g_xb);   p_xb   = (float*)t;
        cudaGetSymbolAddress(&t, g_sc);   p_sc   = (float*)t;
        cudaGetSymbolAddress(&t, g_sb);   p_sb   = (float*)t;
        cudaGetSymbolAddress(&t, g_ahi);  p_ahi  = (__nv_bfloat16*)t;
        cudaGetSymbolAddress(&t, g_alo);  p_alo  = (__nv_bfloat16*)t;
        cudaGetSymbolAddress(&t, g_uhi);  p_uhi  = (__nv_bfloat16*)t;
        cudaGetSymbolAddress(&t, g_ulo);  p_ulo  = (__nv_bfloat16*)t;
        cudaGetSymbolAddress(&t, g_zthi); p_zthi = (__nv_bfloat16*)t;
        cudaGetSymbolAddress(&t, g_ztlo); p_ztlo = (__nv_bfloat16*)t;
        cudaGetSymbolAddress(&t, g_athi); p_athi = (__nv_bfloat16*)t;
        cudaGetSymbolAddress(&t, g_atlo); p_atlo = (__nv_bfloat16*)t;
        cudaFuncSetAttribute(gemm_bf16_kernel,
                             cudaFuncAttributeMaxDynamicSharedMemorySize, HSMEM);
    }

    const int n4_x = (Bq * Lq * Dd) / 4;

    copy_split_kernel<<<n4_x / 256, 256>>>(x_in, x, p_ahi, p_alo, n4_x);
    init_ws_kernel<<<(Bq * Sn * Dd + 255) / 256, 256>>>(ws0);

    for (int it = 0; it < NBi; ++it) {
        rms_logits_kernel<<<Bq * Lq, 256>>>(x, pre_w, compete_w, compete_b);
        topk_xc_kernel<<<Bq * Sn, 256>>>(x);
        // written = xc @ write_w.T + write_b
        gemm_small_split<<<dim3(Dd / 64, 4, KS), 256>>>(0, write_w);
        gemm_small_reduce<<<dim3(64 * Dd / 256, 1), 256>>>(0, write_b);
        ws_update_kernel<<<Bq * Sn, 256>>>(post_w);
        // kk / vv from ws
        gemm_small_split<<<dim3(Dd / 64, 4, KS * 2), 256>>>(1, in_proj_w + (size_t)Dd * Dd);
        gemm_small_reduce<<<dim3(64 * Dd / 256, 2), 256>>>(1, in_proj_b + Dd);
        // u = kk.wq (+ sb = bq.kk); zt = Wo.vv  — tiny K=64 builds, fp32 in, bf16 hi/lo out
        u_build_kernel<<<dim3(Dd / 128, Hn, Bq), 256>>>(in_proj_w, in_proj_b);
        z_build_kernel<<<dim3(Dd / 64, Hn, Bq), 256>>>(out_proj_w);
        // scores[b,l,j] = x.u^T + sb   (M=2048/b, N=512, K=2048)
        gemm_bf16_kernel<<<dim3(SH / 128, Lq / 128, Bq), 256, HSMEM>>>(
            p_ahi, p_alo, p_uhi, p_ulo, p_sb, p_sc,
            Dd, SH, (size_t)Lq * Dd, (size_t)SH * Dd, (size_t)Lq * SH, SH);
        // softmax over 16 slots per head -> att hi/lo
        attn_softmax_kernel<<<Bq * Lq, 256>>>();
        // x_b[b,l,n] = att.zt^T + out_b   (M=2048/b, N=2048, K=512)
        gemm_bf16_kernel<<<dim3(Dd / 128, Lq / 128, Bq), 256, HSMEM>>>(
            p_athi, p_atlo, p_zthi, p_ztlo, out_proj_b, p_xb,
            SH, Dd, (size_t)Lq * SH, (size_t)Dd * SH, (size_t)Lq * Dd, 0);
        // x = RMS(x + x_b); also refresh x hi/lo for next iteration
        resid_rms_kernel<<<Bq * Lq, 256>>>(x, post_w);
    }
}